// round 12
// baseline (speedup 1.0000x reference)
#include <cuda_runtime.h>

// Problem constants
#define NQ 4
#define DIM 16
#define T_STEPS 200
#define NROTS 40      // 5*NQ*NL, NL=2
#define QFF_NROTS 20
#define DEG 3
#define THREADS 256
#define NWARPS (THREADS / 32)
#define NSLOT 68      // gate-table slots per timestep (coeff folded into gate 0)
#define GRID_PERSIST 592   // 148 SMs x 4 CTAs/SM = one resident wave

#define SMEM_FLOATS (NSLOT * T_STEPS + 32 + 32 + NWARPS * 32)

typedef unsigned long long u64;

// ---------- packed f32x2 primitives ----------
__device__ __forceinline__ u64 pk2(float lo, float hi) {
    u64 r; asm("mov.b64 %0, {%1, %2};" : "=l"(r) : "f"(lo), "f"(hi)); return r;
}
__device__ __forceinline__ void upk2(u64 v, float& lo, float& hi) {
    asm("mov.b64 {%0, %1}, %2;" : "=f"(lo), "=f"(hi) : "l"(v));
}
__device__ __forceinline__ u64 swap2(u64 v) {
    float lo, hi; upk2(v, lo, hi); return pk2(hi, lo);
}
__device__ __forceinline__ u64 fma2(u64 a, u64 b, u64 c) {
    u64 d; asm("fma.rn.f32x2 %0, %1, %2, %3;" : "=l"(d) : "l"(a), "l"(b), "l"(c)); return d;
}
__device__ __forceinline__ u64 mul2(u64 a, u64 b) {
    u64 d; asm("mul.rn.f32x2 %0, %1, %2;" : "=l"(d) : "l"(a), "l"(b)); return d;
}

// ---------- packed gates on state vr[8], vi[8] (pack j = amplitudes 2j, 2j+1) ----------

// General 2x2 gate (coeff-folded), qubit pack-weight PW.
template<int PW>
__device__ __forceinline__ void su2_gen(float g00r, float g00i, float g01r, float g01i,
                                        float g10r, float g10i, float g11r, float g11i,
                                        u64* vr, u64* vi) {
    u64 A  = pk2(g00r, g00r), Ai = pk2(g00i, g00i), nAi = pk2(-g00i, -g00i);
    u64 B  = pk2(g01r, g01r), Bi = pk2(g01i, g01i), nBi = pk2(-g01i, -g01i);
    u64 C  = pk2(g10r, g10r), Ci = pk2(g10i, g10i), nCi = pk2(-g10i, -g10i);
    u64 D  = pk2(g11r, g11r), Di = pk2(g11i, g11i), nDi = pk2(-g11i, -g11i);
#pragma unroll
    for (int j = 0; j < 8; j++) {
        if (!(j & PW)) {
            const int q = j | PW;
            u64 r0 = vr[j], i0 = vi[j], r1 = vr[q], i1 = vi[q];
            vr[j] = fma2(A, r0, fma2(nAi, i0, fma2(B, r1, mul2(nBi, i1))));
            vi[j] = fma2(A, i0, fma2(Ai,  r0, fma2(B, i1, mul2(Bi,  r1))));
            vr[q] = fma2(C, r0, fma2(nCi, i0, fma2(D, r1, mul2(nDi, i1))));
            vi[q] = fma2(C, i0, fma2(Ci,  r0, fma2(D, i1, mul2(Di,  r1))));
        }
    }
}

// Fused SU(2), qubit pack-weight PW in {4,2,1}.
template<int PW>
__device__ __forceinline__ void su2_pk(float u00r, float u00i, float u01r, float u01i,
                                       u64* vr, u64* vi) {
    u64 A   = pk2(u00r, u00r),  Ai  = pk2(u00i, u00i),  nAi = pk2(-u00i, -u00i);
    u64 B   = pk2(u01r, u01r),  nB  = pk2(-u01r, -u01r);
    u64 Bi  = pk2(u01i, u01i),  nBi = pk2(-u01i, -u01i);
#pragma unroll
    for (int j = 0; j < 8; j++) {
        if (!(j & PW)) {
            const int q = j | PW;
            u64 r0 = vr[j], i0 = vi[j], r1 = vr[q], i1 = vi[q];
            vr[j] = fma2(A, r0, fma2(nAi, i0, fma2(B,  r1, mul2(nBi, i1))));
            vi[j] = fma2(A, i0, fma2(Ai,  r0, fma2(B,  i1, mul2(Bi,  r1))));
            vr[q] = fma2(A, r1, fma2(Ai,  i1, fma2(nB, r0, mul2(nBi, i0))));
            vi[q] = fma2(A, i1, fma2(nAi, r1, fma2(nB, i0, mul2(Bi,  r0))));
        }
    }
}

// Fused SU(2), qubit weight 1 (partner inside pack; swapped-operand form).
__device__ __forceinline__ void su2_w1(float u00r, float u00i, float u01r, float u01i,
                                       u64* vr, u64* vi) {
    u64 P  = pk2(u00r,  u00r);
    u64 Q  = pk2(u01r, -u01r);
    u64 R  = pk2(-u00i, u00i);
    u64 S  = pk2(-u01i, -u01i);
    u64 R2 = pk2(u00i, -u00i);
    u64 S2 = pk2(u01i,  u01i);
#pragma unroll
    for (int j = 0; j < 8; j++) {
        u64 rp = vr[j], ip = vi[j];
        u64 rs = swap2(rp), is = swap2(ip);
        vr[j] = fma2(P, rp, fma2(Q, rs, fma2(R,  ip, mul2(S,  is))));
        vi[j] = fma2(P, ip, fma2(Q, is, fma2(R2, rp, mul2(S2, rs))));
    }
}

// CRX, control pack-weight PCW, target pack-weight PPW.
template<int PCW, int PPW>
__device__ __forceinline__ void crx_pk(float c, float s, u64* vr, u64* vi) {
    u64 C = pk2(c, c), Sp = pk2(s, s), nS = pk2(-s, -s);
#pragma unroll
    for (int j = 0; j < 8; j++) {
        if ((j & PCW) && !(j & PPW)) {
            const int q = j | PPW;
            u64 r0 = vr[j], i0 = vi[j], r1 = vr[q], i1 = vi[q];
            vr[j] = fma2(C, r0, mul2(Sp, i1));
            vi[j] = fma2(C, i0, mul2(nS, r1));
            vr[q] = fma2(C, r1, mul2(Sp, i0));
            vi[q] = fma2(C, i1, mul2(nS, r0));
        }
    }
}

// CRX with control weight 1 (control bit = half index): masked coeffs.
template<int PPW>
__device__ __forceinline__ void crx_cw1(float c, float s, u64* vr, u64* vi) {
    u64 C = pk2(1.0f, c), Sp = pk2(0.0f, s), nS = pk2(0.0f, -s);
#pragma unroll
    for (int j = 0; j < 8; j++) {
        if (!(j & PPW)) {
            const int q = j | PPW;
            u64 r0 = vr[j], i0 = vi[j], r1 = vr[q], i1 = vi[q];
            vr[j] = fma2(C, r0, mul2(Sp, i1));
            vi[j] = fma2(C, i0, mul2(nS, r1));
            vr[q] = fma2(C, r1, mul2(Sp, i0));
            vi[q] = fma2(C, i1, mul2(nS, r0));
        }
    }
}

// CRX with target weight 1 (pair inside pack), control pack-weight PCW.
template<int PCW>
__device__ __forceinline__ void crx_tw1(float c, float s, u64* vr, u64* vi) {
    u64 C = pk2(c, c), Sp = pk2(s, s), nS = pk2(-s, -s);
#pragma unroll
    for (int j = 0; j < 8; j++) {
        if (j & PCW) {
            u64 rs = swap2(vr[j]), is = swap2(vi[j]);
            vr[j] = fma2(C, vr[j], mul2(Sp, is));
            vi[j] = fma2(C, vi[j], mul2(nS, rs));
        }
    }
}

// ---------- fused single-qubit SU(2) from 3 angles (precompute) ----------
__device__ __forceinline__ void fuse_su2(float pa, float pb, float pg,
                                         float& u00r, float& u00i,
                                         float& u01r, float& u01i) {
    float ca, sa, cb, sb, cg, sg;
    __sincosf(0.5f * pa, &sa, &ca);
    __sincosf(0.5f * pb, &sb, &cb);
    __sincosf(0.5f * pg, &sg, &cg);
    float cbca = cb * ca, cbsa = cb * sa, sbca = sb * ca, sbsa = sb * sa;
    u00r = fmaf(cg, cbca,  sg * sbsa);
    u00i = fmaf(cg, sbsa, -sg * cbca);
    u01r = -fmaf(cg, sbca,  sg * cbsa);
    u01i = fmaf(sg, sbca, -cg * cbsa);
}

// ---------- scalar rotations (epilogue only) ----------
__device__ __forceinline__ void rot_rx(float c, float s,
                                       float& r0, float& i0, float& r1, float& i1) {
    float nr0 = fmaf(c, r0,  s * i1);
    float ni0 = fmaf(c, i0, -s * r1);
    float nr1 = fmaf(c, r1,  s * i0);
    float ni1 = fmaf(c, i1, -s * r0);
    r0 = nr0; i0 = ni0; r1 = nr1; i1 = ni1;
}
__device__ __forceinline__ void rot_ry(float c, float s,
                                       float& r0, float& i0, float& r1, float& i1) {
    float nr0 = fmaf(c, r0, -s * r1);
    float ni0 = fmaf(c, i0, -s * i1);
    float nr1 = fmaf(c, r1,  s * r0);
    float ni1 = fmaf(c, i1,  s * i0);
    r0 = nr0; i0 = ni0; r1 = nr1; i1 = ni1;
}
__device__ __forceinline__ void rot_rz(float c, float s,
                                       float& r0, float& i0, float& r1, float& i1) {
    float nr0 = fmaf(c, r0,  s * i0);
    float ni0 = fmaf(c, i0, -s * r0);
    float nr1 = fmaf(c, r1, -s * i1);
    float ni1 = fmaf(c, i1,  s * r1);
    r0 = nr0; i0 = ni0; r1 = nr1; i1 = ni1;
}
template<int W>
__device__ __forceinline__ void g_rx(float c, float s, float* sr, float* si) {
#pragma unroll
    for (int i = 0; i < DIM; i++)
        if (!(i & W)) rot_rx(c, s, sr[i], si[i], sr[i | W], si[i | W]);
}
template<int W>
__device__ __forceinline__ void g_ry(float c, float s, float* sr, float* si) {
#pragma unroll
    for (int i = 0; i < DIM; i++)
        if (!(i & W)) rot_ry(c, s, sr[i], si[i], sr[i | W], si[i | W]);
}
template<int W>
__device__ __forceinline__ void g_rz(float c, float s, float* sr, float* si) {
#pragma unroll
    for (int i = 0; i < DIM; i++)
        if (!(i & W)) rot_rz(c, s, sr[i], si[i], sr[i | W], si[i | W]);
}
template<int CW, int TW>
__device__ __forceinline__ void g_crx(float c, float s, float* sr, float* si) {
#pragma unroll
    for (int i = 0; i < DIM; i++)
        if ((i & CW) && !(i & TW)) rot_rx(c, s, sr[i], si[i], sr[i | TW], si[i | TW]);
}
__device__ __forceinline__ void ansatz_layer_ref(const float* p, float* sr, float* si) {
    float c, s;
    __sincosf(0.5f * p[0],  &s, &c); g_rx<8>(c, s, sr, si);
    __sincosf(0.5f * p[1],  &s, &c); g_ry<8>(c, s, sr, si);
    __sincosf(0.5f * p[2],  &s, &c); g_rz<8>(c, s, sr, si);
    __sincosf(0.5f * p[3],  &s, &c); g_rx<4>(c, s, sr, si);
    __sincosf(0.5f * p[4],  &s, &c); g_ry<4>(c, s, sr, si);
    __sincosf(0.5f * p[5],  &s, &c); g_rz<4>(c, s, sr, si);
    __sincosf(0.5f * p[6],  &s, &c); g_rx<2>(c, s, sr, si);
    __sincosf(0.5f * p[7],  &s, &c); g_ry<2>(c, s, sr, si);
    __sincosf(0.5f * p[8],  &s, &c); g_rz<2>(c, s, sr, si);
    __sincosf(0.5f * p[9],  &s, &c); g_rx<1>(c, s, sr, si);
    __sincosf(0.5f * p[10], &s, &c); g_ry<1>(c, s, sr, si);
    __sincosf(0.5f * p[11], &s, &c); g_rz<1>(c, s, sr, si);
    __sincosf(0.5f * p[12], &s, &c); g_crx<8, 4>(c, s, sr, si);
    __sincosf(0.5f * p[13], &s, &c); g_crx<4, 2>(c, s, sr, si);
    __sincosf(0.5f * p[14], &s, &c); g_crx<2, 1>(c, s, sr, si);
    __sincosf(0.5f * p[15], &s, &c); g_crx<1, 8>(c, s, sr, si);
    __sincosf(0.5f * p[16], &s, &c); g_crx<1, 2>(c, s, sr, si);
    __sincosf(0.5f * p[17], &s, &c); g_crx<2, 4>(c, s, sr, si);
    __sincosf(0.5f * p[18], &s, &c); g_crx<4, 8>(c, s, sr, si);
    __sincosf(0.5f * p[19], &s, &c); g_crx<8, 1>(c, s, sr, si);
}

__global__ __launch_bounds__(THREADS, 4)
void qac_kernel(const float* __restrict__ tsp,      // (B, T, 40)
                const float* __restrict__ poly,     // (4,)
                const float* __restrict__ mix_re,   // (200,)
                const float* __restrict__ mix_im,   // (200,)
                const float* __restrict__ qff,      // (20,)
                float* __restrict__ out,            // (B, 12)
                int B)
{
    extern __shared__ float sm[];
    float* tab  = sm;                       // [NSLOT][T_STEPS], transposed (4B lane stride)
    float* wv   = sm + NSLOT * T_STEPS;     // 32 (8B-aligned)
    float* accv = wv + 32;                  // 32
    float* part = accv + 32;                // NWARPS*32

    const int tid  = threadIdx.x;
    const int lane = tid & 31;
    const int warp = tid >> 5;

    // Persistent CTA: loop over batches with grid stride.
    for (int b = blockIdx.x; b < B; b += gridDim.x) {

        // ---- Precompute: per-timestep gate table (built once, reused for 3 k) ----
        if (tid < T_STEPS) {
            const float4* p4 = (const float4*)(tsp + (size_t)b * (T_STEPS * NROTS) + tid * NROTS);
            float* col = tab + tid;
            const float cr = mix_re[tid], ci = mix_im[tid];

            float4 v0 = p4[0], v1 = p4[1], v2 = p4[2];
            {
                float u00r, u00i, u01r, u01i;
                fuse_su2(v0.x, v0.y, v0.z, u00r, u00i, u01r, u01i);
                // coeff-folded general 2x2: G = (cr + i*ci) * U
                col[0 * T_STEPS] = cr * u00r - ci * u00i;           // G00r
                col[1 * T_STEPS] = cr * u00i + ci * u00r;           // G00i
                col[2 * T_STEPS] = cr * u01r - ci * u01i;           // G01r
                col[3 * T_STEPS] = cr * u01i + ci * u01r;           // G01i
                col[4 * T_STEPS] = -(cr * u01r + ci * u01i);        // G10r
                col[5 * T_STEPS] = cr * u01i - ci * u01r;           // G10i
                col[6 * T_STEPS] = cr * u00r + ci * u00i;           // G11r
                col[7 * T_STEPS] = ci * u00r - cr * u00i;           // G11i
            }
            {
                float a, bq, g, d;
                fuse_su2(v0.w, v1.x, v1.y, a, bq, g, d);
                col[8  * T_STEPS] = a;  col[9  * T_STEPS] = bq;
                col[10 * T_STEPS] = g;  col[11 * T_STEPS] = d;
                fuse_su2(v1.z, v1.w, v2.x, a, bq, g, d);
                col[12 * T_STEPS] = a;  col[13 * T_STEPS] = bq;
                col[14 * T_STEPS] = g;  col[15 * T_STEPS] = d;
                fuse_su2(v2.y, v2.z, v2.w, a, bq, g, d);
                col[16 * T_STEPS] = a;  col[17 * T_STEPS] = bq;
                col[18 * T_STEPS] = g;  col[19 * T_STEPS] = d;
            }
            {
                float4 c0 = p4[3], c1 = p4[4];
                float ang[8] = {c0.x, c0.y, c0.z, c0.w, c1.x, c1.y, c1.z, c1.w};
#pragma unroll
                for (int g = 0; g < 8; g++) {
                    float c, s;
                    __sincosf(0.5f * ang[g], &s, &c);
                    col[(20 + 2 * g) * T_STEPS] = c;
                    col[(21 + 2 * g) * T_STEPS] = s;
                }
            }
            float4 v3 = p4[5], v4 = p4[6], v5 = p4[7];
            {
                float a, bq, g, d;
                fuse_su2(v3.x, v3.y, v3.z, a, bq, g, d);
                col[36 * T_STEPS] = a;  col[37 * T_STEPS] = bq;
                col[38 * T_STEPS] = g;  col[39 * T_STEPS] = d;
                fuse_su2(v3.w, v4.x, v4.y, a, bq, g, d);
                col[40 * T_STEPS] = a;  col[41 * T_STEPS] = bq;
                col[42 * T_STEPS] = g;  col[43 * T_STEPS] = d;
                fuse_su2(v4.z, v4.w, v5.x, a, bq, g, d);
                col[44 * T_STEPS] = a;  col[45 * T_STEPS] = bq;
                col[46 * T_STEPS] = g;  col[47 * T_STEPS] = d;
                fuse_su2(v5.y, v5.z, v5.w, a, bq, g, d);
                col[48 * T_STEPS] = a;  col[49 * T_STEPS] = bq;
                col[50 * T_STEPS] = g;  col[51 * T_STEPS] = d;
            }
            {
                float4 c2 = p4[8], c3 = p4[9];
                float ang[8] = {c2.x, c2.y, c2.z, c2.w, c3.x, c3.y, c3.z, c3.w};
#pragma unroll
                for (int g = 0; g < 8; g++) {
                    float c, s;
                    __sincosf(0.5f * ang[g], &s, &c);
                    col[(52 + 2 * g) * T_STEPS] = c;
                    col[(53 + 2 * g) * T_STEPS] = s;
                }
            }
        }
        if (tid < 32) {
            wv[tid]   = (tid == 0) ? 1.0f : 0.0f;
            accv[tid] = (tid == 0) ? poly[0] : 0.0f;
        }
        __syncthreads();

        const float* col = tab + tid;

        // ---- QSVT iterations: work_k = sum_t (c_t U_t) work_{k-1} (coeff in table) ----
#pragma unroll 1
        for (int k = 1; k <= DEG; k++) {
            float a[32];
            if (tid < T_STEPS) {
                u64 vr[8], vi[8];
                const u64* wv64 = (const u64*)wv;
#pragma unroll
                for (int j = 0; j < 8; j++) { vr[j] = wv64[j]; vi[j] = wv64[8 + j]; }

                // layer 0 (gate 0 carries the LCU coefficient)
                su2_gen<4>(col[0 * T_STEPS], col[1 * T_STEPS], col[2 * T_STEPS], col[3 * T_STEPS],
                           col[4 * T_STEPS], col[5 * T_STEPS], col[6 * T_STEPS], col[7 * T_STEPS],
                           vr, vi);
                su2_pk<2>(col[8  * T_STEPS], col[9  * T_STEPS],
                          col[10 * T_STEPS], col[11 * T_STEPS], vr, vi);
                su2_pk<1>(col[12 * T_STEPS], col[13 * T_STEPS],
                          col[14 * T_STEPS], col[15 * T_STEPS], vr, vi);
                su2_w1  (col[16 * T_STEPS], col[17 * T_STEPS],
                         col[18 * T_STEPS], col[19 * T_STEPS], vr, vi);
                crx_pk<4, 2>(col[20 * T_STEPS], col[21 * T_STEPS], vr, vi);  // <8,4>
                crx_pk<2, 1>(col[22 * T_STEPS], col[23 * T_STEPS], vr, vi);  // <4,2>
                crx_tw1<1>  (col[24 * T_STEPS], col[25 * T_STEPS], vr, vi);  // <2,1>
                crx_cw1<4>  (col[26 * T_STEPS], col[27 * T_STEPS], vr, vi);  // <1,8>
                crx_cw1<1>  (col[28 * T_STEPS], col[29 * T_STEPS], vr, vi);  // <1,2>
                crx_pk<1, 2>(col[30 * T_STEPS], col[31 * T_STEPS], vr, vi);  // <2,4>
                crx_pk<2, 4>(col[32 * T_STEPS], col[33 * T_STEPS], vr, vi);  // <4,8>
                crx_tw1<4>  (col[34 * T_STEPS], col[35 * T_STEPS], vr, vi);  // <8,1>

                // layer 1
                su2_pk<4>(col[36 * T_STEPS], col[37 * T_STEPS],
                          col[38 * T_STEPS], col[39 * T_STEPS], vr, vi);
                su2_pk<2>(col[40 * T_STEPS], col[41 * T_STEPS],
                          col[42 * T_STEPS], col[43 * T_STEPS], vr, vi);
                su2_pk<1>(col[44 * T_STEPS], col[45 * T_STEPS],
                          col[46 * T_STEPS], col[47 * T_STEPS], vr, vi);
                su2_w1  (col[48 * T_STEPS], col[49 * T_STEPS],
                         col[50 * T_STEPS], col[51 * T_STEPS], vr, vi);
                crx_pk<4, 2>(col[52 * T_STEPS], col[53 * T_STEPS], vr, vi);
                crx_pk<2, 1>(col[54 * T_STEPS], col[55 * T_STEPS], vr, vi);
                crx_tw1<1>  (col[56 * T_STEPS], col[57 * T_STEPS], vr, vi);
                crx_cw1<4>  (col[58 * T_STEPS], col[59 * T_STEPS], vr, vi);
                crx_cw1<1>  (col[60 * T_STEPS], col[61 * T_STEPS], vr, vi);
                crx_pk<1, 2>(col[62 * T_STEPS], col[63 * T_STEPS], vr, vi);
                crx_pk<2, 4>(col[64 * T_STEPS], col[65 * T_STEPS], vr, vi);
                crx_tw1<4>  (col[66 * T_STEPS], col[67 * T_STEPS], vr, vi);

#pragma unroll
                for (int j = 0; j < 8; j++) {
                    upk2(vr[j], a[2 * j],      a[2 * j + 1]);
                    upk2(vi[j], a[16 + 2 * j], a[17 + 2 * j]);
                }
            } else {
#pragma unroll
                for (int q = 0; q < 32; q++) a[q] = 0.0f;
            }

            // Payload-splitting warp reduction: 31 SHFL total.
#pragma unroll
            for (int m = 16; m >= 1; m >>= 1) {
                const bool hi = (lane & m) != 0;
#pragma unroll
                for (int s = 0; s < m; s++) {
                    float snd = hi ? a[s] : a[s + m];
                    float kep = hi ? a[s + m] : a[s];
                    a[s] = kep + __shfl_xor_sync(0xffffffffu, snd, m);
                }
            }
            part[warp * 32 + lane] = a[0];
            __syncthreads();
            if (tid < 32) {
                float sum = 0.0f;
#pragma unroll
                for (int w = 0; w < NWARPS; w++) sum += part[w * 32 + tid];
                wv[tid] = sum;
                accv[tid] = fmaf(poly[k], sum, accv[tid]);
            }
            __syncthreads();
        }

        // ---- Epilogue: normalize, QFF ansatz, expectation values ----
        if (tid == 0) {
            float l1 = fabsf(poly[0]) + fabsf(poly[1]) + fabsf(poly[2]) + fabsf(poly[3]);
            float inv_l1 = 1.0f / l1;
            float sr[16], si[16];
            float n2 = 0.0f;
#pragma unroll
            for (int q = 0; q < 16; q++) {
                sr[q] = accv[q] * inv_l1;
                si[q] = accv[16 + q] * inv_l1;
                n2 = fmaf(sr[q], sr[q], fmaf(si[q], si[q], n2));
            }
            float inv_n = 1.0f / (sqrtf(n2) + 1e-9f);
#pragma unroll
            for (int q = 0; q < 16; q++) { sr[q] *= inv_n; si[q] *= inv_n; }

            float qp[QFF_NROTS];
#pragma unroll
            for (int j = 0; j < QFF_NROTS; j++) qp[j] = qff[j];
            ansatz_layer_ref(qp, sr, si);

            float* o = out + b * 12;
#pragma unroll
            for (int qi = 0; qi < NQ; qi++) {
                const int W = 8 >> qi;
                float X = 0.0f, Y = 0.0f, Z = 0.0f;
#pragma unroll
                for (int i0 = 0; i0 < DIM; i0++) {
                    if (!(i0 & W)) {
                        int j0 = i0 | W;
                        X += 2.0f * (sr[i0] * sr[j0] + si[i0] * si[j0]);
                        Y += 2.0f * (sr[i0] * si[j0] - si[i0] * sr[j0]);
                        Z += (sr[i0] * sr[i0] + si[i0] * si[i0])
                           - (sr[j0] * sr[j0] + si[j0] * si[j0]);
                    }
                }
                o[qi] = X; o[4 + qi] = Y; o[8 + qi] = Z;
            }
        }
        __syncthreads();   // protect tab/wv/accv reuse before next batch
    }
}

extern "C" void kernel_launch(void* const* d_in, const int* in_sizes, int n_in,
                              void* d_out, int out_size) {
    const float* tsp    = (const float*)d_in[0];
    const float* poly   = (const float*)d_in[1];
    const float* mix_re = (const float*)d_in[2];
    const float* mix_im = (const float*)d_in[3];
    const float* qff    = (const float*)d_in[4];
    float* out = (float*)d_out;
    int B = in_sizes[0] / (T_STEPS * NROTS);   // 2048

    int grid = (B < GRID_PERSIST) ? B : GRID_PERSIST;
    const int smem_bytes = SMEM_FLOATS * sizeof(float);   // ~55.5KB
    cudaFuncSetAttribute(qac_kernel, cudaFuncAttributeMaxDynamicSharedMemorySize, smem_bytes);
    qac_kernel<<<grid, THREADS, smem_bytes>>>(tsp, poly, mix_re, mix_im, qff, out, B);
}

// round 15
// speedup vs baseline: 1.1757x; 1.1757x over previous
#include <cuda_runtime.h>

// Problem constants
#define NQ 4
#define DIM 16
#define T_STEPS 200
#define NROTS 40      // 5*NQ*NL, NL=2
#define QFF_NROTS 20
#define DEG 3
#define THREADS 256
#define NSLOT 68      // gate-table slots per timestep (coeff folded into gate 0)

#define SMEM_FLOATS (NSLOT * T_STEPS + 32 + 32 + 8 * 32)

typedef unsigned long long u64;

// ---------- packed f32x2 primitives ----------
__device__ __forceinline__ u64 pk2(float lo, float hi) {
    u64 r; asm("mov.b64 %0, {%1, %2};" : "=l"(r) : "f"(lo), "f"(hi)); return r;
}
__device__ __forceinline__ void upk2(u64 v, float& lo, float& hi) {
    asm("mov.b64 {%0, %1}, %2;" : "=f"(lo), "=f"(hi) : "l"(v));
}
__device__ __forceinline__ u64 swap2(u64 v) {
    float lo, hi; upk2(v, lo, hi); return pk2(hi, lo);
}
__device__ __forceinline__ u64 fma2(u64 a, u64 b, u64 c) {
    u64 d; asm("fma.rn.f32x2 %0, %1, %2, %3;" : "=l"(d) : "l"(a), "l"(b), "l"(c)); return d;
}
__device__ __forceinline__ u64 mul2(u64 a, u64 b) {
    u64 d; asm("mul.rn.f32x2 %0, %1, %2;" : "=l"(d) : "l"(a), "l"(b)); return d;
}

// ---------- packed gates on state vr[8], vi[8] (pack j = amplitudes 2j, 2j+1) ----------

// General 2x2 gate (coeff-folded), qubit pack-weight PW.
template<int PW>
__device__ __forceinline__ void su2_gen(float g00r, float g00i, float g01r, float g01i,
                                        float g10r, float g10i, float g11r, float g11i,
                                        u64* vr, u64* vi) {
    u64 A  = pk2(g00r, g00r), Ai = pk2(g00i, g00i), nAi = pk2(-g00i, -g00i);
    u64 B  = pk2(g01r, g01r), Bi = pk2(g01i, g01i), nBi = pk2(-g01i, -g01i);
    u64 C  = pk2(g10r, g10r), Ci = pk2(g10i, g10i), nCi = pk2(-g10i, -g10i);
    u64 D  = pk2(g11r, g11r), Di = pk2(g11i, g11i), nDi = pk2(-g11i, -g11i);
#pragma unroll
    for (int j = 0; j < 8; j++) {
        if (!(j & PW)) {
            const int q = j | PW;
            u64 r0 = vr[j], i0 = vi[j], r1 = vr[q], i1 = vi[q];
            vr[j] = fma2(A, r0, fma2(nAi, i0, fma2(B, r1, mul2(nBi, i1))));
            vi[j] = fma2(A, i0, fma2(Ai,  r0, fma2(B, i1, mul2(Bi,  r1))));
            vr[q] = fma2(C, r0, fma2(nCi, i0, fma2(D, r1, mul2(nDi, i1))));
            vi[q] = fma2(C, i0, fma2(Ci,  r0, fma2(D, i1, mul2(Di,  r1))));
        }
    }
}

// Fused SU(2), qubit pack-weight PW in {4,2,1}.
template<int PW>
__device__ __forceinline__ void su2_pk(float u00r, float u00i, float u01r, float u01i,
                                       u64* vr, u64* vi) {
    u64 A   = pk2(u00r, u00r),  Ai  = pk2(u00i, u00i),  nAi = pk2(-u00i, -u00i);
    u64 B   = pk2(u01r, u01r),  nB  = pk2(-u01r, -u01r);
    u64 Bi  = pk2(u01i, u01i),  nBi = pk2(-u01i, -u01i);
#pragma unroll
    for (int j = 0; j < 8; j++) {
        if (!(j & PW)) {
            const int q = j | PW;
            u64 r0 = vr[j], i0 = vi[j], r1 = vr[q], i1 = vi[q];
            vr[j] = fma2(A, r0, fma2(nAi, i0, fma2(B,  r1, mul2(nBi, i1))));
            vi[j] = fma2(A, i0, fma2(Ai,  r0, fma2(B,  i1, mul2(Bi,  r1))));
            vr[q] = fma2(A, r1, fma2(Ai,  i1, fma2(nB, r0, mul2(nBi, i0))));
            vi[q] = fma2(A, i1, fma2(nAi, r1, fma2(nB, i0, mul2(Bi,  r0))));
        }
    }
}

// Fused SU(2), qubit weight 1 (partner inside pack; swapped-operand form).
__device__ __forceinline__ void su2_w1(float u00r, float u00i, float u01r, float u01i,
                                       u64* vr, u64* vi) {
    u64 P  = pk2(u00r,  u00r);
    u64 Q  = pk2(u01r, -u01r);
    u64 R  = pk2(-u00i, u00i);
    u64 S  = pk2(-u01i, -u01i);
    u64 R2 = pk2(u00i, -u00i);
    u64 S2 = pk2(u01i,  u01i);
#pragma unroll
    for (int j = 0; j < 8; j++) {
        u64 rp = vr[j], ip = vi[j];
        u64 rs = swap2(rp), is = swap2(ip);
        vr[j] = fma2(P, rp, fma2(Q, rs, fma2(R,  ip, mul2(S,  is))));
        vi[j] = fma2(P, ip, fma2(Q, is, fma2(R2, rp, mul2(S2, rs))));
    }
}

// CRX, control pack-weight PCW, target pack-weight PPW.
template<int PCW, int PPW>
__device__ __forceinline__ void crx_pk(float c, float s, u64* vr, u64* vi) {
    u64 C = pk2(c, c), Sp = pk2(s, s), nS = pk2(-s, -s);
#pragma unroll
    for (int j = 0; j < 8; j++) {
        if ((j & PCW) && !(j & PPW)) {
            const int q = j | PPW;
            u64 r0 = vr[j], i0 = vi[j], r1 = vr[q], i1 = vi[q];
            vr[j] = fma2(C, r0, mul2(Sp, i1));
            vi[j] = fma2(C, i0, mul2(nS, r1));
            vr[q] = fma2(C, r1, mul2(Sp, i0));
            vi[q] = fma2(C, i1, mul2(nS, r0));
        }
    }
}

// CRX with control weight 1 (control bit = half index): masked coeffs.
template<int PPW>
__device__ __forceinline__ void crx_cw1(float c, float s, u64* vr, u64* vi) {
    u64 C = pk2(1.0f, c), Sp = pk2(0.0f, s), nS = pk2(0.0f, -s);
#pragma unroll
    for (int j = 0; j < 8; j++) {
        if (!(j & PPW)) {
            const int q = j | PPW;
            u64 r0 = vr[j], i0 = vi[j], r1 = vr[q], i1 = vi[q];
            vr[j] = fma2(C, r0, mul2(Sp, i1));
            vi[j] = fma2(C, i0, mul2(nS, r1));
            vr[q] = fma2(C, r1, mul2(Sp, i0));
            vi[q] = fma2(C, i1, mul2(nS, r0));
        }
    }
}

// CRX with target weight 1 (pair inside pack), control pack-weight PCW.
template<int PCW>
__device__ __forceinline__ void crx_tw1(float c, float s, u64* vr, u64* vi) {
    u64 C = pk2(c, c), Sp = pk2(s, s), nS = pk2(-s, -s);
#pragma unroll
    for (int j = 0; j < 8; j++) {
        if (j & PCW) {
            u64 rs = swap2(vr[j]), is = swap2(vi[j]);
            vr[j] = fma2(C, vr[j], mul2(Sp, is));
            vi[j] = fma2(C, vi[j], mul2(nS, rs));
        }
    }
}

// ---------- fused single-qubit SU(2) from 3 angles (precompute) ----------
__device__ __forceinline__ void fuse_su2(float pa, float pb, float pg,
                                         float& u00r, float& u00i,
                                         float& u01r, float& u01i) {
    float ca, sa, cb, sb, cg, sg;
    __sincosf(0.5f * pa, &sa, &ca);
    __sincosf(0.5f * pb, &sb, &cb);
    __sincosf(0.5f * pg, &sg, &cg);
    float cbca = cb * ca, cbsa = cb * sa, sbca = sb * ca, sbsa = sb * sa;
    u00r = fmaf(cg, cbca,  sg * sbsa);
    u00i = fmaf(cg, sbsa, -sg * cbca);
    u01r = -fmaf(cg, sbca,  sg * cbsa);
    u01i = fmaf(sg, sbca, -cg * cbsa);
}

// ---------- scalar rotations (epilogue only) ----------
__device__ __forceinline__ void rot_rx(float c, float s,
                                       float& r0, float& i0, float& r1, float& i1) {
    float nr0 = fmaf(c, r0,  s * i1);
    float ni0 = fmaf(c, i0, -s * r1);
    float nr1 = fmaf(c, r1,  s * i0);
    float ni1 = fmaf(c, i1, -s * r0);
    r0 = nr0; i0 = ni0; r1 = nr1; i1 = ni1;
}
__device__ __forceinline__ void rot_ry(float c, float s,
                                       float& r0, float& i0, float& r1, float& i1) {
    float nr0 = fmaf(c, r0, -s * r1);
    float ni0 = fmaf(c, i0, -s * i1);
    float nr1 = fmaf(c, r1,  s * r0);
    float ni1 = fmaf(c, i1,  s * i0);
    r0 = nr0; i0 = ni0; r1 = nr1; i1 = ni1;
}
__device__ __forceinline__ void rot_rz(float c, float s,
                                       float& r0, float& i0, float& r1, float& i1) {
    float nr0 = fmaf(c, r0,  s * i0);
    float ni0 = fmaf(c, i0, -s * r0);
    float nr1 = fmaf(c, r1, -s * i1);
    float ni1 = fmaf(c, i1,  s * r1);
    r0 = nr0; i0 = ni0; r1 = nr1; i1 = ni1;
}
template<int W>
__device__ __forceinline__ void g_rx(float c, float s, float* sr, float* si) {
#pragma unroll
    for (int i = 0; i < DIM; i++)
        if (!(i & W)) rot_rx(c, s, sr[i], si[i], sr[i | W], si[i | W]);
}
template<int W>
__device__ __forceinline__ void g_ry(float c, float s, float* sr, float* si) {
#pragma unroll
    for (int i = 0; i < DIM; i++)
        if (!(i & W)) rot_ry(c, s, sr[i], si[i], sr[i | W], si[i | W]);
}
template<int W>
__device__ __forceinline__ void g_rz(float c, float s, float* sr, float* si) {
#pragma unroll
    for (int i = 0; i < DIM; i++)
        if (!(i & W)) rot_rz(c, s, sr[i], si[i], sr[i | W], si[i | W]);
}
template<int CW, int TW>
__device__ __forceinline__ void g_crx(float c, float s, float* sr, float* si) {
#pragma unroll
    for (int i = 0; i < DIM; i++)
        if ((i & CW) && !(i & TW)) rot_rx(c, s, sr[i], si[i], sr[i | TW], si[i | TW]);
}
__device__ __forceinline__ void ansatz_layer_ref(const float* p, float* sr, float* si) {
    float c, s;
    __sincosf(0.5f * p[0],  &s, &c); g_rx<8>(c, s, sr, si);
    __sincosf(0.5f * p[1],  &s, &c); g_ry<8>(c, s, sr, si);
    __sincosf(0.5f * p[2],  &s, &c); g_rz<8>(c, s, sr, si);
    __sincosf(0.5f * p[3],  &s, &c); g_rx<4>(c, s, sr, si);
    __sincosf(0.5f * p[4],  &s, &c); g_ry<4>(c, s, sr, si);
    __sincosf(0.5f * p[5],  &s, &c); g_rz<4>(c, s, sr, si);
    __sincosf(0.5f * p[6],  &s, &c); g_rx<2>(c, s, sr, si);
    __sincosf(0.5f * p[7],  &s, &c); g_ry<2>(c, s, sr, si);
    __sincosf(0.5f * p[8],  &s, &c); g_rz<2>(c, s, sr, si);
    __sincosf(0.5f * p[9],  &s, &c); g_rx<1>(c, s, sr, si);
    __sincosf(0.5f * p[10], &s, &c); g_ry<1>(c, s, sr, si);
    __sincosf(0.5f * p[11], &s, &c); g_rz<1>(c, s, sr, si);
    __sincosf(0.5f * p[12], &s, &c); g_crx<8, 4>(c, s, sr, si);
    __sincosf(0.5f * p[13], &s, &c); g_crx<4, 2>(c, s, sr, si);
    __sincosf(0.5f * p[14], &s, &c); g_crx<2, 1>(c, s, sr, si);
    __sincosf(0.5f * p[15], &s, &c); g_crx<1, 8>(c, s, sr, si);
    __sincosf(0.5f * p[16], &s, &c); g_crx<1, 2>(c, s, sr, si);
    __sincosf(0.5f * p[17], &s, &c); g_crx<2, 4>(c, s, sr, si);
    __sincosf(0.5f * p[18], &s, &c); g_crx<4, 8>(c, s, sr, si);
    __sincosf(0.5f * p[19], &s, &c); g_crx<8, 1>(c, s, sr, si);
}

__global__ __launch_bounds__(THREADS, 4)
void qac_kernel(const float* __restrict__ tsp,      // (B, T, 40)
                const float* __restrict__ poly,     // (4,)
                const float* __restrict__ mix_re,   // (200,)
                const float* __restrict__ mix_im,   // (200,)
                const float* __restrict__ qff,      // (20,)
                float* __restrict__ out)            // (B, 12)
{
    extern __shared__ float sm[];
    float* tab  = sm;                       // [NSLOT][T_STEPS], transposed (4B lane stride)
    float* wv   = sm + NSLOT * T_STEPS;     // 32 (8B-aligned)
    float* accv = wv + 32;                  // 32
    float* part = accv + 32;                // 8*32

    const int b    = blockIdx.x;
    const int tid  = threadIdx.x;
    const int lane = tid & 31;
    const int warp = tid >> 5;

    // ---- Precompute: per-timestep gate table (built once, reused for 3 k) ----
    if (tid < T_STEPS) {
        const float4* p4 = (const float4*)(tsp + (size_t)b * (T_STEPS * NROTS) + tid * NROTS);
        float* col = tab + tid;
        const float cr = mix_re[tid], ci = mix_im[tid];

        float4 v0 = p4[0], v1 = p4[1], v2 = p4[2];
        {
            float u00r, u00i, u01r, u01i;
            fuse_su2(v0.x, v0.y, v0.z, u00r, u00i, u01r, u01i);
            // coeff-folded general 2x2: G = (cr + i*ci) * U
            col[0 * T_STEPS] = cr * u00r - ci * u00i;           // G00r
            col[1 * T_STEPS] = cr * u00i + ci * u00r;           // G00i
            col[2 * T_STEPS] = cr * u01r - ci * u01i;           // G01r
            col[3 * T_STEPS] = cr * u01i + ci * u01r;           // G01i
            col[4 * T_STEPS] = -(cr * u01r + ci * u01i);        // G10r
            col[5 * T_STEPS] = cr * u01i - ci * u01r;           // G10i
            col[6 * T_STEPS] = cr * u00r + ci * u00i;           // G11r
            col[7 * T_STEPS] = ci * u00r - cr * u00i;           // G11i
        }
        {
            float a, bq, g, d;
            fuse_su2(v0.w, v1.x, v1.y, a, bq, g, d);
            col[8  * T_STEPS] = a;  col[9  * T_STEPS] = bq;
            col[10 * T_STEPS] = g;  col[11 * T_STEPS] = d;
            fuse_su2(v1.z, v1.w, v2.x, a, bq, g, d);
            col[12 * T_STEPS] = a;  col[13 * T_STEPS] = bq;
            col[14 * T_STEPS] = g;  col[15 * T_STEPS] = d;
            fuse_su2(v2.y, v2.z, v2.w, a, bq, g, d);
            col[16 * T_STEPS] = a;  col[17 * T_STEPS] = bq;
            col[18 * T_STEPS] = g;  col[19 * T_STEPS] = d;
        }
        {
            float4 c0 = p4[3], c1 = p4[4];
            float ang[8] = {c0.x, c0.y, c0.z, c0.w, c1.x, c1.y, c1.z, c1.w};
#pragma unroll
            for (int g = 0; g < 8; g++) {
                float c, s;
                __sincosf(0.5f * ang[g], &s, &c);
                col[(20 + 2 * g) * T_STEPS] = c;
                col[(21 + 2 * g) * T_STEPS] = s;
            }
        }
        float4 v3 = p4[5], v4 = p4[6], v5 = p4[7];
        {
            float a, bq, g, d;
            fuse_su2(v3.x, v3.y, v3.z, a, bq, g, d);
            col[36 * T_STEPS] = a;  col[37 * T_STEPS] = bq;
            col[38 * T_STEPS] = g;  col[39 * T_STEPS] = d;
            fuse_su2(v3.w, v4.x, v4.y, a, bq, g, d);
            col[40 * T_STEPS] = a;  col[41 * T_STEPS] = bq;
            col[42 * T_STEPS] = g;  col[43 * T_STEPS] = d;
            fuse_su2(v4.z, v4.w, v5.x, a, bq, g, d);
            col[44 * T_STEPS] = a;  col[45 * T_STEPS] = bq;
            col[46 * T_STEPS] = g;  col[47 * T_STEPS] = d;
            fuse_su2(v5.y, v5.z, v5.w, a, bq, g, d);
            col[48 * T_STEPS] = a;  col[49 * T_STEPS] = bq;
            col[50 * T_STEPS] = g;  col[51 * T_STEPS] = d;
        }
        {
            float4 c2 = p4[8], c3 = p4[9];
            float ang[8] = {c2.x, c2.y, c2.z, c2.w, c3.x, c3.y, c3.z, c3.w};
#pragma unroll
            for (int g = 0; g < 8; g++) {
                float c, s;
                __sincosf(0.5f * ang[g], &s, &c);
                col[(52 + 2 * g) * T_STEPS] = c;
                col[(53 + 2 * g) * T_STEPS] = s;
            }
        }
    }
    if (tid < 32) {
        wv[tid]   = (tid == 0) ? 1.0f : 0.0f;
        accv[tid] = (tid == 0) ? poly[0] : 0.0f;
    }
    __syncthreads();

    const float* col = tab + tid;

    // ---- QSVT iterations: work_k = sum_t (c_t U_t) work_{k-1} (coeff in table) ----
#pragma unroll 1
    for (int k = 1; k <= DEG; k++) {
        float a[32];
        if (tid < T_STEPS) {
            u64 vr[8], vi[8];
            const u64* wv64 = (const u64*)wv;
#pragma unroll
            for (int j = 0; j < 8; j++) { vr[j] = wv64[j]; vi[j] = wv64[8 + j]; }

            // layer 0 (gate 0 carries the LCU coefficient)
            su2_gen<4>(col[0 * T_STEPS], col[1 * T_STEPS], col[2 * T_STEPS], col[3 * T_STEPS],
                       col[4 * T_STEPS], col[5 * T_STEPS], col[6 * T_STEPS], col[7 * T_STEPS],
                       vr, vi);
            su2_pk<2>(col[8  * T_STEPS], col[9  * T_STEPS],
                      col[10 * T_STEPS], col[11 * T_STEPS], vr, vi);
            su2_pk<1>(col[12 * T_STEPS], col[13 * T_STEPS],
                      col[14 * T_STEPS], col[15 * T_STEPS], vr, vi);
            su2_w1  (col[16 * T_STEPS], col[17 * T_STEPS],
                     col[18 * T_STEPS], col[19 * T_STEPS], vr, vi);
            crx_pk<4, 2>(col[20 * T_STEPS], col[21 * T_STEPS], vr, vi);  // <8,4>
            crx_pk<2, 1>(col[22 * T_STEPS], col[23 * T_STEPS], vr, vi);  // <4,2>
            crx_tw1<1>  (col[24 * T_STEPS], col[25 * T_STEPS], vr, vi);  // <2,1>
            crx_cw1<4>  (col[26 * T_STEPS], col[27 * T_STEPS], vr, vi);  // <1,8>
            crx_cw1<1>  (col[28 * T_STEPS], col[29 * T_STEPS], vr, vi);  // <1,2>
            crx_pk<1, 2>(col[30 * T_STEPS], col[31 * T_STEPS], vr, vi);  // <2,4>
            crx_pk<2, 4>(col[32 * T_STEPS], col[33 * T_STEPS], vr, vi);  // <4,8>
            crx_tw1<4>  (col[34 * T_STEPS], col[35 * T_STEPS], vr, vi);  // <8,1>

            // layer 1
            su2_pk<4>(col[36 * T_STEPS], col[37 * T_STEPS],
                      col[38 * T_STEPS], col[39 * T_STEPS], vr, vi);
            su2_pk<2>(col[40 * T_STEPS], col[41 * T_STEPS],
                      col[42 * T_STEPS], col[43 * T_STEPS], vr, vi);
            su2_pk<1>(col[44 * T_STEPS], col[45 * T_STEPS],
                      col[46 * T_STEPS], col[47 * T_STEPS], vr, vi);
            su2_w1  (col[48 * T_STEPS], col[49 * T_STEPS],
                     col[50 * T_STEPS], col[51 * T_STEPS], vr, vi);
            crx_pk<4, 2>(col[52 * T_STEPS], col[53 * T_STEPS], vr, vi);
            crx_pk<2, 1>(col[54 * T_STEPS], col[55 * T_STEPS], vr, vi);
            crx_tw1<1>  (col[56 * T_STEPS], col[57 * T_STEPS], vr, vi);
            crx_cw1<4>  (col[58 * T_STEPS], col[59 * T_STEPS], vr, vi);
            crx_cw1<1>  (col[60 * T_STEPS], col[61 * T_STEPS], vr, vi);
            crx_pk<1, 2>(col[62 * T_STEPS], col[63 * T_STEPS], vr, vi);
            crx_pk<2, 4>(col[64 * T_STEPS], col[65 * T_STEPS], vr, vi);
            crx_tw1<4>  (col[66 * T_STEPS], col[67 * T_STEPS], vr, vi);

#pragma unroll
            for (int j = 0; j < 8; j++) {
                upk2(vr[j], a[2 * j],      a[2 * j + 1]);
                upk2(vi[j], a[16 + 2 * j], a[17 + 2 * j]);
            }
        } else {
#pragma unroll
            for (int q = 0; q < 32; q++) a[q] = 0.0f;
        }

        // Payload-splitting warp reduction: 31 SHFL total.
#pragma unroll
        for (int m = 16; m >= 1; m >>= 1) {
            const bool hi = (lane & m) != 0;
#pragma unroll
            for (int s = 0; s < m; s++) {
                float snd = hi ? a[s] : a[s + m];
                float kep = hi ? a[s + m] : a[s];
                a[s] = kep + __shfl_xor_sync(0xffffffffu, snd, m);
            }
        }
        part[warp * 32 + lane] = a[0];
        __syncthreads();
        if (tid < 32) {
            float sum = 0.0f;
#pragma unroll
            for (int w = 0; w < THREADS / 32; w++) sum += part[w * 32 + tid];
            wv[tid] = sum;
            accv[tid] = fmaf(poly[k], sum, accv[tid]);
        }
        __syncthreads();
    }

    // ---- Epilogue ----
    if (tid == 0) {
        float l1 = fabsf(poly[0]) + fabsf(poly[1]) + fabsf(poly[2]) + fabsf(poly[3]);
        float inv_l1 = 1.0f / l1;
        float sr[16], si[16];
        float n2 = 0.0f;
#pragma unroll
        for (int q = 0; q < 16; q++) {
            sr[q] = accv[q] * inv_l1;
            si[q] = accv[16 + q] * inv_l1;
            n2 = fmaf(sr[q], sr[q], fmaf(si[q], si[q], n2));
        }
        float inv_n = 1.0f / (sqrtf(n2) + 1e-9f);
#pragma unroll
        for (int q = 0; q < 16; q++) { sr[q] *= inv_n; si[q] *= inv_n; }

        float qp[QFF_NROTS];
#pragma unroll
        for (int j = 0; j < QFF_NROTS; j++) qp[j] = qff[j];
        ansatz_layer_ref(qp, sr, si);

        float* o = out + b * 12;
#pragma unroll
        for (int qi = 0; qi < NQ; qi++) {
            const int W = 8 >> qi;
            float X = 0.0f, Y = 0.0f, Z = 0.0f;
#pragma unroll
            for (int i0 = 0; i0 < DIM; i0++) {
                if (!(i0 & W)) {
                    int j0 = i0 | W;
                    X += 2.0f * (sr[i0] * sr[j0] + si[i0] * si[j0]);
                    Y += 2.0f * (sr[i0] * si[j0] - si[i0] * sr[j0]);
                    Z += (sr[i0] * sr[i0] + si[i0] * si[i0])
                       - (sr[j0] * sr[j0] + si[j0] * si[j0]);
                }
            }
            o[qi] = X; o[4 + qi] = Y; o[8 + qi] = Z;
        }
    }
}

extern "C" void kernel_launch(void* const* d_in, const int* in_sizes, int n_in,
                              void* d_out, int out_size) {
    const float* tsp    = (const float*)d_in[0];
    const float* poly   = (const float*)d_in[1];
    const float* mix_re = (const float*)d_in[2];
    const float* mix_im = (const float*)d_in[3];
    const float* qff    = (const float*)d_in[4];
    float* out = (float*)d_out;
    int B = in_sizes[0] / (T_STEPS * NROTS);   // 2048

    const int smem_bytes = SMEM_FLOATS * sizeof(float);   // ~55.7KB
    cudaFuncSetAttribute(qac_kernel, cudaFuncAttributeMaxDynamicSharedMemorySize, smem_bytes);
    qac_kernel<<<B, THREADS, smem_bytes>>>(tsp, poly, mix_re, mix_im, qff, out);
}

// round 16
// speedup vs baseline: 1.2199x; 1.0377x over previous
#include <cuda_runtime.h>

// Problem constants
#define NQ 4
#define DIM 16
#define T_STEPS 200
#define NROTS 40      // 5*NQ*NL, NL=2
#define QFF_NROTS 20
#define DEG 3
#define THREADS 256
#define NSLOT 68      // gate-table slots per timestep (coeff folded into gate 0)

#define SMEM_FLOATS (NSLOT * T_STEPS + 32 + 32 + 8 * 32)

typedef unsigned long long u64;

// ---------- packed f32x2 primitives ----------
__device__ __forceinline__ u64 pk2(float lo, float hi) {
    u64 r; asm("mov.b64 %0, {%1, %2};" : "=l"(r) : "f"(lo), "f"(hi)); return r;
}
__device__ __forceinline__ void upk2(u64 v, float& lo, float& hi) {
    asm("mov.b64 {%0, %1}, %2;" : "=f"(lo), "=f"(hi) : "l"(v));
}
__device__ __forceinline__ u64 swap2(u64 v) {
    float lo, hi; upk2(v, lo, hi); return pk2(hi, lo);
}
__device__ __forceinline__ u64 fma2(u64 a, u64 b, u64 c) {
    u64 d; asm("fma.rn.f32x2 %0, %1, %2, %3;" : "=l"(d) : "l"(a), "l"(b), "l"(c)); return d;
}
__device__ __forceinline__ u64 mul2(u64 a, u64 b) {
    u64 d; asm("mul.rn.f32x2 %0, %1, %2;" : "=l"(d) : "l"(a), "l"(b)); return d;
}

// ---------- packed gates on state vr[8], vi[8] (pack j = amplitudes 2j, 2j+1) ----------

// General 2x2 gate (coeff-folded), qubit pack-weight PW.
template<int PW>
__device__ __forceinline__ void su2_gen(float g00r, float g00i, float g01r, float g01i,
                                        float g10r, float g10i, float g11r, float g11i,
                                        u64* vr, u64* vi) {
    u64 A  = pk2(g00r, g00r), Ai = pk2(g00i, g00i), nAi = pk2(-g00i, -g00i);
    u64 B  = pk2(g01r, g01r), Bi = pk2(g01i, g01i), nBi = pk2(-g01i, -g01i);
    u64 C  = pk2(g10r, g10r), Ci = pk2(g10i, g10i), nCi = pk2(-g10i, -g10i);
    u64 D  = pk2(g11r, g11r), Di = pk2(g11i, g11i), nDi = pk2(-g11i, -g11i);
#pragma unroll
    for (int j = 0; j < 8; j++) {
        if (!(j & PW)) {
            const int q = j | PW;
            u64 r0 = vr[j], i0 = vi[j], r1 = vr[q], i1 = vi[q];
            vr[j] = fma2(A, r0, fma2(nAi, i0, fma2(B, r1, mul2(nBi, i1))));
            vi[j] = fma2(A, i0, fma2(Ai,  r0, fma2(B, i1, mul2(Bi,  r1))));
            vr[q] = fma2(C, r0, fma2(nCi, i0, fma2(D, r1, mul2(nDi, i1))));
            vi[q] = fma2(C, i0, fma2(Ci,  r0, fma2(D, i1, mul2(Di,  r1))));
        }
    }
}

// Fused SU(2), qubit pack-weight PW in {4,2,1}.
template<int PW>
__device__ __forceinline__ void su2_pk(float u00r, float u00i, float u01r, float u01i,
                                       u64* vr, u64* vi) {
    u64 A   = pk2(u00r, u00r),  Ai  = pk2(u00i, u00i),  nAi = pk2(-u00i, -u00i);
    u64 B   = pk2(u01r, u01r),  nB  = pk2(-u01r, -u01r);
    u64 Bi  = pk2(u01i, u01i),  nBi = pk2(-u01i, -u01i);
#pragma unroll
    for (int j = 0; j < 8; j++) {
        if (!(j & PW)) {
            const int q = j | PW;
            u64 r0 = vr[j], i0 = vi[j], r1 = vr[q], i1 = vi[q];
            vr[j] = fma2(A, r0, fma2(nAi, i0, fma2(B,  r1, mul2(nBi, i1))));
            vi[j] = fma2(A, i0, fma2(Ai,  r0, fma2(B,  i1, mul2(Bi,  r1))));
            vr[q] = fma2(A, r1, fma2(Ai,  i1, fma2(nB, r0, mul2(nBi, i0))));
            vi[q] = fma2(A, i1, fma2(nAi, r1, fma2(nB, i0, mul2(Bi,  r0))));
        }
    }
}

// Fused SU(2), qubit weight 1 (partner inside pack; swapped-operand form).
__device__ __forceinline__ void su2_w1(float u00r, float u00i, float u01r, float u01i,
                                       u64* vr, u64* vi) {
    u64 P  = pk2(u00r,  u00r);
    u64 Q  = pk2(u01r, -u01r);
    u64 R  = pk2(-u00i, u00i);
    u64 S  = pk2(-u01i, -u01i);
    u64 R2 = pk2(u00i, -u00i);
    u64 S2 = pk2(u01i,  u01i);
#pragma unroll
    for (int j = 0; j < 8; j++) {
        u64 rp = vr[j], ip = vi[j];
        u64 rs = swap2(rp), is = swap2(ip);
        vr[j] = fma2(P, rp, fma2(Q, rs, fma2(R,  ip, mul2(S,  is))));
        vi[j] = fma2(P, ip, fma2(Q, is, fma2(R2, rp, mul2(S2, rs))));
    }
}

// CRX, control pack-weight PCW, target pack-weight PPW.
template<int PCW, int PPW>
__device__ __forceinline__ void crx_pk(float c, float s, u64* vr, u64* vi) {
    u64 C = pk2(c, c), Sp = pk2(s, s), nS = pk2(-s, -s);
#pragma unroll
    for (int j = 0; j < 8; j++) {
        if ((j & PCW) && !(j & PPW)) {
            const int q = j | PPW;
            u64 r0 = vr[j], i0 = vi[j], r1 = vr[q], i1 = vi[q];
            vr[j] = fma2(C, r0, mul2(Sp, i1));
            vi[j] = fma2(C, i0, mul2(nS, r1));
            vr[q] = fma2(C, r1, mul2(Sp, i0));
            vi[q] = fma2(C, i1, mul2(nS, r0));
        }
    }
}

// CRX with control weight 1 (control bit = half index): masked coeffs.
template<int PPW>
__device__ __forceinline__ void crx_cw1(float c, float s, u64* vr, u64* vi) {
    u64 C = pk2(1.0f, c), Sp = pk2(0.0f, s), nS = pk2(0.0f, -s);
#pragma unroll
    for (int j = 0; j < 8; j++) {
        if (!(j & PPW)) {
            const int q = j | PPW;
            u64 r0 = vr[j], i0 = vi[j], r1 = vr[q], i1 = vi[q];
            vr[j] = fma2(C, r0, mul2(Sp, i1));
            vi[j] = fma2(C, i0, mul2(nS, r1));
            vr[q] = fma2(C, r1, mul2(Sp, i0));
            vi[q] = fma2(C, i1, mul2(nS, r0));
        }
    }
}

// CRX with target weight 1 (pair inside pack), control pack-weight PCW.
template<int PCW>
__device__ __forceinline__ void crx_tw1(float c, float s, u64* vr, u64* vi) {
    u64 C = pk2(c, c), Sp = pk2(s, s), nS = pk2(-s, -s);
#pragma unroll
    for (int j = 0; j < 8; j++) {
        if (j & PCW) {
            u64 rs = swap2(vr[j]), is = swap2(vi[j]);
            vr[j] = fma2(C, vr[j], mul2(Sp, is));
            vi[j] = fma2(C, vi[j], mul2(nS, rs));
        }
    }
}

// ---------- fused single-qubit SU(2) from 3 angles (precompute) ----------
__device__ __forceinline__ void fuse_su2(float pa, float pb, float pg,
                                         float& u00r, float& u00i,
                                         float& u01r, float& u01i) {
    float ca, sa, cb, sb, cg, sg;
    __sincosf(0.5f * pa, &sa, &ca);
    __sincosf(0.5f * pb, &sb, &cb);
    __sincosf(0.5f * pg, &sg, &cg);
    float cbca = cb * ca, cbsa = cb * sa, sbca = sb * ca, sbsa = sb * sa;
    u00r = fmaf(cg, cbca,  sg * sbsa);
    u00i = fmaf(cg, sbsa, -sg * cbca);
    u01r = -fmaf(cg, sbca,  sg * cbsa);
    u01i = fmaf(sg, sbca, -cg * cbsa);
}

// ---------- scalar rotations (epilogue only) ----------
__device__ __forceinline__ void rot_rx(float c, float s,
                                       float& r0, float& i0, float& r1, float& i1) {
    float nr0 = fmaf(c, r0,  s * i1);
    float ni0 = fmaf(c, i0, -s * r1);
    float nr1 = fmaf(c, r1,  s * i0);
    float ni1 = fmaf(c, i1, -s * r0);
    r0 = nr0; i0 = ni0; r1 = nr1; i1 = ni1;
}
__device__ __forceinline__ void rot_ry(float c, float s,
                                       float& r0, float& i0, float& r1, float& i1) {
    float nr0 = fmaf(c, r0, -s * r1);
    float ni0 = fmaf(c, i0, -s * i1);
    float nr1 = fmaf(c, r1,  s * r0);
    float ni1 = fmaf(c, i1,  s * i0);
    r0 = nr0; i0 = ni0; r1 = nr1; i1 = ni1;
}
__device__ __forceinline__ void rot_rz(float c, float s,
                                       float& r0, float& i0, float& r1, float& i1) {
    float nr0 = fmaf(c, r0,  s * i0);
    float ni0 = fmaf(c, i0, -s * r0);
    float nr1 = fmaf(c, r1, -s * i1);
    float ni1 = fmaf(c, i1,  s * r1);
    r0 = nr0; i0 = ni0; r1 = nr1; i1 = ni1;
}
template<int W>
__device__ __forceinline__ void g_rx(float c, float s, float* sr, float* si) {
#pragma unroll
    for (int i = 0; i < DIM; i++)
        if (!(i & W)) rot_rx(c, s, sr[i], si[i], sr[i | W], si[i | W]);
}
template<int W>
__device__ __forceinline__ void g_ry(float c, float s, float* sr, float* si) {
#pragma unroll
    for (int i = 0; i < DIM; i++)
        if (!(i & W)) rot_ry(c, s, sr[i], si[i], sr[i | W], si[i | W]);
}
template<int W>
__device__ __forceinline__ void g_rz(float c, float s, float* sr, float* si) {
#pragma unroll
    for (int i = 0; i < DIM; i++)
        if (!(i & W)) rot_rz(c, s, sr[i], si[i], sr[i | W], si[i | W]);
}
template<int CW, int TW>
__device__ __forceinline__ void g_crx(float c, float s, float* sr, float* si) {
#pragma unroll
    for (int i = 0; i < DIM; i++)
        if ((i & CW) && !(i & TW)) rot_rx(c, s, sr[i], si[i], sr[i | TW], si[i | TW]);
}
__device__ __forceinline__ void ansatz_layer_ref(const float* p, float* sr, float* si) {
    float c, s;
    __sincosf(0.5f * p[0],  &s, &c); g_rx<8>(c, s, sr, si);
    __sincosf(0.5f * p[1],  &s, &c); g_ry<8>(c, s, sr, si);
    __sincosf(0.5f * p[2],  &s, &c); g_rz<8>(c, s, sr, si);
    __sincosf(0.5f * p[3],  &s, &c); g_rx<4>(c, s, sr, si);
    __sincosf(0.5f * p[4],  &s, &c); g_ry<4>(c, s, sr, si);
    __sincosf(0.5f * p[5],  &s, &c); g_rz<4>(c, s, sr, si);
    __sincosf(0.5f * p[6],  &s, &c); g_rx<2>(c, s, sr, si);
    __sincosf(0.5f * p[7],  &s, &c); g_ry<2>(c, s, sr, si);
    __sincosf(0.5f * p[8],  &s, &c); g_rz<2>(c, s, sr, si);
    __sincosf(0.5f * p[9],  &s, &c); g_rx<1>(c, s, sr, si);
    __sincosf(0.5f * p[10], &s, &c); g_ry<1>(c, s, sr, si);
    __sincosf(0.5f * p[11], &s, &c); g_rz<1>(c, s, sr, si);
    __sincosf(0.5f * p[12], &s, &c); g_crx<8, 4>(c, s, sr, si);
    __sincosf(0.5f * p[13], &s, &c); g_crx<4, 2>(c, s, sr, si);
    __sincosf(0.5f * p[14], &s, &c); g_crx<2, 1>(c, s, sr, si);
    __sincosf(0.5f * p[15], &s, &c); g_crx<1, 8>(c, s, sr, si);
    __sincosf(0.5f * p[16], &s, &c); g_crx<1, 2>(c, s, sr, si);
    __sincosf(0.5f * p[17], &s, &c); g_crx<2, 4>(c, s, sr, si);
    __sincosf(0.5f * p[18], &s, &c); g_crx<4, 8>(c, s, sr, si);
    __sincosf(0.5f * p[19], &s, &c); g_crx<8, 1>(c, s, sr, si);
}

__global__ __launch_bounds__(THREADS, 4)
void qac_kernel(const float* __restrict__ tsp,      // (B, T, 40)
                const float* __restrict__ poly,     // (4,)
                const float* __restrict__ mix_re,   // (200,)
                const float* __restrict__ mix_im,   // (200,)
                const float* __restrict__ qff,      // (20,)
                float* __restrict__ out)            // (B, 12)
{
    extern __shared__ float sm[];
    float* tab  = sm;                       // [NSLOT][T_STEPS], transposed (4B lane stride)
    float* wv   = sm + NSLOT * T_STEPS;     // 32 (8B-aligned)
    float* accv = wv + 32;                  // 32
    float* part = accv + 32;                // 8*32

    const int b    = blockIdx.x;
    const int tid  = threadIdx.x;
    const int lane = tid & 31;
    const int warp = tid >> 5;

    // ---- Precompute: per-timestep gate table (built once, reused for 3 k) ----
    if (tid < T_STEPS) {
        const float4* p4 = (const float4*)(tsp + (size_t)b * (T_STEPS * NROTS) + tid * NROTS);
        float* col = tab + tid;
        const float cr = mix_re[tid], ci = mix_im[tid];

        float4 v0 = p4[0], v1 = p4[1], v2 = p4[2];
        {
            float u00r, u00i, u01r, u01i;
            fuse_su2(v0.x, v0.y, v0.z, u00r, u00i, u01r, u01i);
            // coeff-folded general 2x2: G = (cr + i*ci) * U
            col[0 * T_STEPS] = cr * u00r - ci * u00i;           // G00r
            col[1 * T_STEPS] = cr * u00i + ci * u00r;           // G00i
            col[2 * T_STEPS] = cr * u01r - ci * u01i;           // G01r
            col[3 * T_STEPS] = cr * u01i + ci * u01r;           // G01i
            col[4 * T_STEPS] = -(cr * u01r + ci * u01i);        // G10r
            col[5 * T_STEPS] = cr * u01i - ci * u01r;           // G10i
            col[6 * T_STEPS] = cr * u00r + ci * u00i;           // G11r
            col[7 * T_STEPS] = ci * u00r - cr * u00i;           // G11i
        }
        {
            float a, bq, g, d;
            fuse_su2(v0.w, v1.x, v1.y, a, bq, g, d);
            col[8  * T_STEPS] = a;  col[9  * T_STEPS] = bq;
            col[10 * T_STEPS] = g;  col[11 * T_STEPS] = d;
            fuse_su2(v1.z, v1.w, v2.x, a, bq, g, d);
            col[12 * T_STEPS] = a;  col[13 * T_STEPS] = bq;
            col[14 * T_STEPS] = g;  col[15 * T_STEPS] = d;
            fuse_su2(v2.y, v2.z, v2.w, a, bq, g, d);
            col[16 * T_STEPS] = a;  col[17 * T_STEPS] = bq;
            col[18 * T_STEPS] = g;  col[19 * T_STEPS] = d;
        }
        {
            float4 c0 = p4[3], c1 = p4[4];
            float ang[8] = {c0.x, c0.y, c0.z, c0.w, c1.x, c1.y, c1.z, c1.w};
#pragma unroll
            for (int g = 0; g < 8; g++) {
                float c, s;
                __sincosf(0.5f * ang[g], &s, &c);
                col[(20 + 2 * g) * T_STEPS] = c;
                col[(21 + 2 * g) * T_STEPS] = s;
            }
        }
        float4 v3 = p4[5], v4 = p4[6], v5 = p4[7];
        {
            float a, bq, g, d;
            fuse_su2(v3.x, v3.y, v3.z, a, bq, g, d);
            col[36 * T_STEPS] = a;  col[37 * T_STEPS] = bq;
            col[38 * T_STEPS] = g;  col[39 * T_STEPS] = d;
            fuse_su2(v3.w, v4.x, v4.y, a, bq, g, d);
            col[40 * T_STEPS] = a;  col[41 * T_STEPS] = bq;
            col[42 * T_STEPS] = g;  col[43 * T_STEPS] = d;
            fuse_su2(v4.z, v4.w, v5.x, a, bq, g, d);
            col[44 * T_STEPS] = a;  col[45 * T_STEPS] = bq;
            col[46 * T_STEPS] = g;  col[47 * T_STEPS] = d;
            fuse_su2(v5.y, v5.z, v5.w, a, bq, g, d);
            col[48 * T_STEPS] = a;  col[49 * T_STEPS] = bq;
            col[50 * T_STEPS] = g;  col[51 * T_STEPS] = d;
        }
        {
            float4 c2 = p4[8], c3 = p4[9];
            float ang[8] = {c2.x, c2.y, c2.z, c2.w, c3.x, c3.y, c3.z, c3.w};
#pragma unroll
            for (int g = 0; g < 8; g++) {
                float c, s;
                __sincosf(0.5f * ang[g], &s, &c);
                col[(52 + 2 * g) * T_STEPS] = c;
                col[(53 + 2 * g) * T_STEPS] = s;
            }
        }
    }
    if (tid < 32) {
        wv[tid]   = (tid == 0) ? 1.0f : 0.0f;
        accv[tid] = (tid == 0) ? poly[0] : 0.0f;
    }
    __syncthreads();

    const float* col = tab + tid;

    // ---- QSVT iterations: work_k = sum_t (c_t U_t) work_{k-1} (coeff in table) ----
#pragma unroll 1
    for (int k = 1; k <= DEG; k++) {
        float a[32];
        if (tid < T_STEPS) {
            u64 vr[8], vi[8];
            const u64* wv64 = (const u64*)wv;
#pragma unroll
            for (int j = 0; j < 8; j++) { vr[j] = wv64[j]; vi[j] = wv64[8 + j]; }

            // layer 0 (gate 0 carries the LCU coefficient)
            su2_gen<4>(col[0 * T_STEPS], col[1 * T_STEPS], col[2 * T_STEPS], col[3 * T_STEPS],
                       col[4 * T_STEPS], col[5 * T_STEPS], col[6 * T_STEPS], col[7 * T_STEPS],
                       vr, vi);
            su2_pk<2>(col[8  * T_STEPS], col[9  * T_STEPS],
                      col[10 * T_STEPS], col[11 * T_STEPS], vr, vi);
            su2_pk<1>(col[12 * T_STEPS], col[13 * T_STEPS],
                      col[14 * T_STEPS], col[15 * T_STEPS], vr, vi);
            su2_w1  (col[16 * T_STEPS], col[17 * T_STEPS],
                     col[18 * T_STEPS], col[19 * T_STEPS], vr, vi);
            crx_pk<4, 2>(col[20 * T_STEPS], col[21 * T_STEPS], vr, vi);  // <8,4>
            crx_pk<2, 1>(col[22 * T_STEPS], col[23 * T_STEPS], vr, vi);  // <4,2>
            crx_tw1<1>  (col[24 * T_STEPS], col[25 * T_STEPS], vr, vi);  // <2,1>
            crx_cw1<4>  (col[26 * T_STEPS], col[27 * T_STEPS], vr, vi);  // <1,8>
            crx_cw1<1>  (col[28 * T_STEPS], col[29 * T_STEPS], vr, vi);  // <1,2>
            crx_pk<1, 2>(col[30 * T_STEPS], col[31 * T_STEPS], vr, vi);  // <2,4>
            crx_pk<2, 4>(col[32 * T_STEPS], col[33 * T_STEPS], vr, vi);  // <4,8>
            crx_tw1<4>  (col[34 * T_STEPS], col[35 * T_STEPS], vr, vi);  // <8,1>

            // layer 1
            su2_pk<4>(col[36 * T_STEPS], col[37 * T_STEPS],
                      col[38 * T_STEPS], col[39 * T_STEPS], vr, vi);
            su2_pk<2>(col[40 * T_STEPS], col[41 * T_STEPS],
                      col[42 * T_STEPS], col[43 * T_STEPS], vr, vi);
            su2_pk<1>(col[44 * T_STEPS], col[45 * T_STEPS],
                      col[46 * T_STEPS], col[47 * T_STEPS], vr, vi);
            su2_w1  (col[48 * T_STEPS], col[49 * T_STEPS],
                     col[50 * T_STEPS], col[51 * T_STEPS], vr, vi);
            crx_pk<4, 2>(col[52 * T_STEPS], col[53 * T_STEPS], vr, vi);
            crx_pk<2, 1>(col[54 * T_STEPS], col[55 * T_STEPS], vr, vi);
            crx_tw1<1>  (col[56 * T_STEPS], col[57 * T_STEPS], vr, vi);
            crx_cw1<4>  (col[58 * T_STEPS], col[59 * T_STEPS], vr, vi);
            crx_cw1<1>  (col[60 * T_STEPS], col[61 * T_STEPS], vr, vi);
            crx_pk<1, 2>(col[62 * T_STEPS], col[63 * T_STEPS], vr, vi);
            crx_pk<2, 4>(col[64 * T_STEPS], col[65 * T_STEPS], vr, vi);
            crx_tw1<4>  (col[66 * T_STEPS], col[67 * T_STEPS], vr, vi);

#pragma unroll
            for (int j = 0; j < 8; j++) {
                upk2(vr[j], a[2 * j],      a[2 * j + 1]);
                upk2(vi[j], a[16 + 2 * j], a[17 + 2 * j]);
            }
        } else {
#pragma unroll
            for (int q = 0; q < 32; q++) a[q] = 0.0f;
        }

        // Payload-splitting warp reduction: 31 SHFL total.
#pragma unroll
        for (int m = 16; m >= 1; m >>= 1) {
            const bool hi = (lane & m) != 0;
#pragma unroll
            for (int s = 0; s < m; s++) {
                float snd = hi ? a[s] : a[s + m];
                float kep = hi ? a[s + m] : a[s];
                a[s] = kep + __shfl_xor_sync(0xffffffffu, snd, m);
            }
        }
        part[warp * 32 + lane] = a[0];
        __syncthreads();
        if (tid < 32) {
            float sum = 0.0f;
#pragma unroll
            for (int w = 0; w < THREADS / 32; w++) sum += part[w * 32 + tid];
            wv[tid] = sum;
            accv[tid] = fmaf(poly[k], sum, accv[tid]);
        }
        __syncthreads();
    }

    // ---- Epilogue ----
    if (tid == 0) {
        float l1 = fabsf(poly[0]) + fabsf(poly[1]) + fabsf(poly[2]) + fabsf(poly[3]);
        float inv_l1 = 1.0f / l1;
        float sr[16], si[16];
        float n2 = 0.0f;
#pragma unroll
        for (int q = 0; q < 16; q++) {
            sr[q] = accv[q] * inv_l1;
            si[q] = accv[16 + q] * inv_l1;
            n2 = fmaf(sr[q], sr[q], fmaf(si[q], si[q], n2));
        }
        float inv_n = 1.0f / (sqrtf(n2) + 1e-9f);
#pragma unroll
        for (int q = 0; q < 16; q++) { sr[q] *= inv_n; si[q] *= inv_n; }

        float qp[QFF_NROTS];
#pragma unroll
        for (int j = 0; j < QFF_NROTS; j++) qp[j] = qff[j];
        ansatz_layer_ref(qp, sr, si);

        float* o = out + b * 12;
#pragma unroll
        for (int qi = 0; qi < NQ; qi++) {
            const int W = 8 >> qi;
            float X = 0.0f, Y = 0.0f, Z = 0.0f;
#pragma unroll
            for (int i0 = 0; i0 < DIM; i0++) {
                if (!(i0 & W)) {
                    int j0 = i0 | W;
                    X += 2.0f * (sr[i0] * sr[j0] + si[i0] * si[j0]);
                    Y += 2.0f * (sr[i0] * si[j0] - si[i0] * sr[j0]);
                    Z += (sr[i0] * sr[i0] + si[i0] * si[i0])
                       - (sr[j0] * sr[j0] + si[j0] * si[j0]);
                }
            }
            o[qi] = X; o[4 + qi] = Y; o[8 + qi] = Z;
        }
    }
}

extern "C" void kernel_launch(void* const* d_in, const int* in_sizes, int n_in,
                              void* d_out, int out_size) {
    const float* tsp    = (const float*)d_in[0];
    const float* poly   = (const float*)d_in[1];
    const float* mix_re = (const float*)d_in[2];
    const float* mix_im = (const float*)d_in[3];
    const float* qff    = (const float*)d_in[4];
    float* out = (float*)d_out;
    int B = in_sizes[0] / (T_STEPS * NROTS);   // 2048

    const int smem_bytes = SMEM_FLOATS * sizeof(float);   // ~55.7KB
    cudaFuncSetAttribute(qac_kernel, cudaFuncAttributeMaxDynamicSharedMemorySize, smem_bytes);
    qac_kernel<<<B, THREADS, smem_bytes>>>(tsp, poly, mix_re, mix_im, qff, out);
}